// round 14
// baseline (speedup 1.0000x reference)
#include <cuda_runtime.h>
#include <cuda_fp16.h>
#include <cstdint>
#include <cstddef>

#define BDIM 16384
#define ADIM 512
#define MDIM 1024
#define INV_TAU 10.0f

constexpr int BM = 256, BN = 128;            // CTA tile
constexpr int A_PLANE = 256 * 128;           // 32 KB (256 rows x 128 B)
constexpr int B_PLANE = 128 * 128;           // 16 KB
// drive: A_hi + A_lo + B = 80 KB/stage, 2 stages
constexpr int DSTAGE = 2 * A_PLANE + B_PLANE;
constexpr int SMEM_DRIVE = 2 * DSTAGE;       // 160 KB
// settle: A + B = 48 KB/stage, 3 stages
constexpr int SSTAGE = A_PLANE + B_PLANE;
constexpr int SMEM_SETTLE = 3 * SSTAGE;      // 144 KB

// ---- device scratch (allocation-free rule) ----
__device__ __align__(128) __half g_xh[(size_t)BDIM * MDIM];
__device__ __align__(128) __half g_xl[(size_t)BDIM * MDIM];
__device__ __align__(128) __half g_wh[(size_t)ADIM * MDIM];
__device__ __align__(128) __half g_jh[(size_t)ADIM * ADIM];
__device__ __align__(128) float g_drive[(size_t)BDIM * ADIM];
__device__ __align__(128) __half g_s0[(size_t)BDIM * ADIM];
__device__ __align__(128) __half g_s1[(size_t)BDIM * ADIM];

// ---- helpers ----
__device__ __forceinline__ void cp16(void* sdst, const void* gsrc) {
    uint32_t s = (uint32_t)__cvta_generic_to_shared(sdst);
    asm volatile("cp.async.cg.shared.global [%0], [%1], 16;\n" ::"r"(s), "l"(gsrc));
}

__device__ __forceinline__ void ldsm4(uint32_t* r, const void* p) {
    uint32_t a = (uint32_t)__cvta_generic_to_shared(p);
    asm volatile("ldmatrix.sync.aligned.m8n8.x4.shared.b16 {%0,%1,%2,%3}, [%4];\n"
                 : "=r"(r[0]), "=r"(r[1]), "=r"(r[2]), "=r"(r[3])
                 : "r"(a));
}

__device__ __forceinline__ void mma_fp16(float* c, const uint32_t* a, const uint32_t* b) {
    asm volatile(
        "mma.sync.aligned.m16n8k16.row.col.f32.f16.f16.f32 "
        "{%0,%1,%2,%3}, {%4,%5,%6,%7}, {%8,%9}, {%0,%1,%2,%3};\n"
        : "+f"(c[0]), "+f"(c[1]), "+f"(c[2]), "+f"(c[3])
        : "r"(a[0]), "r"(a[1]), "r"(a[2]), "r"(a[3]), "r"(b[0]), "r"(b[1]));
}

// 128B-row swizzle: rows of 64 fp16, 8 chunks of 16B
__device__ __forceinline__ uint32_t swz128(int r, int ch) {
    return (uint32_t)(r * 128 + ((ch ^ (r & 7)) << 4));
}

__device__ __forceinline__ float fast_tanh(float x) {
    float e, r;
    asm("ex2.approx.f32 %0, %1;" : "=f"(e) : "f"(x * 2.8853901817f));
    asm("rcp.approx.f32 %0, %1;" : "=f"(r) : "f"(e + 1.0f));
    return fmaf(-2.0f, r, 1.0f);
}

// ---- split fp32 -> fp16 hi/lo (x) ----
__global__ void split_h(const float4* __restrict__ src, uint2* __restrict__ hi,
                        uint2* __restrict__ lo, int n4) {
    int i = blockIdx.x * blockDim.x + threadIdx.x;
    if (i >= n4) return;
    float4 v = src[i];
    float f[4] = {v.x, v.y, v.z, v.w};
    uint16_t h[4], l[4];
#pragma unroll
    for (int k = 0; k < 4; k++) {
        __half hb = __float2half_rn(f[k]);
        __half lb = __float2half_rn(f[k] - __half2float(hb));
        h[k] = __half_as_ushort(hb);
        l[k] = __half_as_ushort(lb);
    }
    hi[i] = make_uint2((uint32_t)h[0] | ((uint32_t)h[1] << 16),
                       (uint32_t)h[2] | ((uint32_t)h[3] << 16));
    lo[i] = make_uint2((uint32_t)l[0] | ((uint32_t)l[1] << 16),
                       (uint32_t)l[2] | ((uint32_t)l[3] << 16));
}

// ---- truncate fp32 -> fp16 (W, J) ----
__global__ void trunc_h(const float4* __restrict__ src, uint2* __restrict__ dst, int n4) {
    int i = blockIdx.x * blockDim.x + threadIdx.x;
    if (i >= n4) return;
    float4 v = src[i];
    __half2 a = __halves2half2(__float2half_rn(v.x), __float2half_rn(v.y));
    __half2 b = __halves2half2(__float2half_rn(v.z), __float2half_rn(v.w));
    dst[i] = make_uint2(*(uint32_t*)&a, *(uint32_t*)&b);
}

// ========== drive: fp16x2 (x exact hi+lo, W truncated), KD=1024 ==========
__global__ void __launch_bounds__(256, 1)
drive_gemm(const __half* __restrict__ Ahi, const __half* __restrict__ Alo,
           const __half* __restrict__ Bw, const float* __restrict__ bias,
           float* __restrict__ of32, __half* __restrict__ osig) {
    constexpr int KD = MDIM;
    constexpr int BK = 64;
    extern __shared__ char sm[];
    const int tid = threadIdx.x, lane = tid & 31, wid = tid >> 5;
    const int wm = wid & 3, wn = wid >> 2;         // 4 x 2 warp grid, 64x64 tiles
    const int rowBase = blockIdx.y * BM, colBase = blockIdx.x * BN;

    float acc[4][8][4];
#pragma unroll
    for (int mi = 0; mi < 4; mi++)
#pragma unroll
        for (int ni = 0; ni < 8; ni++)
#pragma unroll
            for (int q = 0; q < 4; q++) acc[mi][ni][q] = 0.f;

    // producers: A 2048 chunks (8/thr), B 1024 chunks (4/thr)
    uint32_t sA[8], gA[8], sB[4], gB[4];
#pragma unroll
    for (int j = 0; j < 8; j++) {
        int c = tid + j * 256, r = c >> 3, ch = c & 7;
        sA[j] = swz128(r, ch);
        gA[j] = (uint32_t)(rowBase + r) * KD + ch * 8;
    }
#pragma unroll
    for (int j = 0; j < 4; j++) {
        int c = tid + j * 256, r = c >> 3, ch = c & 7;
        sB[j] = swz128(r, ch);
        gB[j] = (uint32_t)(colBase + r) * KD + ch * 8;
    }

    auto issue = [&](int kt, int s) {
        char* st = sm + s * DSTAGE;
        const uint32_t kof = kt * BK;
#pragma unroll
        for (int j = 0; j < 8; j++) {
            cp16(st + sA[j], Ahi + gA[j] + kof);
            cp16(st + A_PLANE + sA[j], Alo + gA[j] + kof);
        }
#pragma unroll
        for (int j = 0; j < 4; j++)
            cp16(st + 2 * A_PLANE + sB[j], Bw + gB[j] + kof);
        asm volatile("cp.async.commit_group;\n");
    };

    const int arowl = lane & 15;
    const int browl = ((lane >> 4) << 3) + (lane & 7);
    const int ac0 = lane >> 4, bc0 = (lane >> 3) & 1;

    constexpr int KT = KD / BK;  // 16
    issue(0, 0);

    for (int kt = 0; kt < KT; kt++) {
        const int buf = kt & 1;
        if (kt + 1 < KT) {
            issue(kt + 1, buf ^ 1);
            asm volatile("cp.async.wait_group 1;\n");
        } else {
            asm volatile("cp.async.wait_group 0;\n");
        }
        __syncthreads();
        char* st = sm + buf * DSTAGE;

#pragma unroll
        for (int k16 = 0; k16 < 4; k16++) {
            uint32_t ah[4][4], al[4][4], bb[4][4];
#pragma unroll
            for (int mi = 0; mi < 4; mi++) {
                uint32_t ao = swz128(wm * 64 + mi * 16 + arowl, k16 * 2 + ac0);
                ldsm4(ah[mi], st + ao);
                ldsm4(al[mi], st + A_PLANE + ao);
            }
#pragma unroll
            for (int g = 0; g < 4; g++)
                ldsm4(bb[g], st + 2 * A_PLANE +
                              swz128(wn * 64 + g * 16 + browl, k16 * 2 + bc0));
#pragma unroll
            for (int ni = 0; ni < 8; ni++) {
                const uint32_t* b = &bb[ni >> 1][(ni & 1) * 2];
#pragma unroll
                for (int mi = 0; mi < 4; mi++) mma_fp16(acc[mi][ni], ah[mi], b);
#pragma unroll
                for (int mi = 0; mi < 4; mi++) mma_fp16(acc[mi][ni], al[mi], b);
            }
        }
        __syncthreads();
    }

    const int lrow = lane >> 2, lcol = lane & 3;
#pragma unroll
    for (int mi = 0; mi < 4; mi++) {
#pragma unroll
        for (int ni = 0; ni < 8; ni++) {
            const int gr = rowBase + wm * 64 + mi * 16 + lrow;
            const int gc = colBase + wn * 64 + ni * 8 + lcol * 2;
            const uint32_t i0 = (uint32_t)gr * ADIM + gc;
            const uint32_t i1 = i0 + 8 * ADIM;
            const float b0 = bias[gc], b1 = bias[gc + 1];
            float v0 = acc[mi][ni][0] + b0, v1 = acc[mi][ni][1] + b1;
            float v2 = acc[mi][ni][2] + b0, v3 = acc[mi][ni][3] + b1;
            *(float2*)(of32 + i0) = make_float2(v0, v1);
            *(float2*)(of32 + i1) = make_float2(v2, v3);
            *(__half2*)(osig + i0) =
                __halves2half2(__float2half_rn(fast_tanh(v0)), __float2half_rn(fast_tanh(v1)));
            *(__half2*)(osig + i1) =
                __halves2half2(__float2half_rn(fast_tanh(v2)), __float2half_rn(fast_tanh(v3)));
        }
    }
}

// ========== settle: fp16 single-pass, KD=512, 3-stage ==========
template <int MODE>
__global__ void __launch_bounds__(256, 1)
settle_fp16(const __half* __restrict__ Asig, const __half* __restrict__ Bj,
            const float* __restrict__ aux, __half* __restrict__ osig,
            float* __restrict__ of32) {
    constexpr int KD = ADIM;
    constexpr int BK = 64;
    constexpr int NS = 3;
    extern __shared__ char sm[];
    const int tid = threadIdx.x, lane = tid & 31, wid = tid >> 5;
    const int wm = wid & 3, wn = wid >> 2;
    const int rowBase = blockIdx.y * BM, colBase = blockIdx.x * BN;

    float acc[4][8][4];
#pragma unroll
    for (int mi = 0; mi < 4; mi++)
#pragma unroll
        for (int ni = 0; ni < 8; ni++)
#pragma unroll
            for (int q = 0; q < 4; q++) acc[mi][ni][q] = 0.f;

    uint32_t sA[8], gA[8], sB[4], gB[4];
#pragma unroll
    for (int j = 0; j < 8; j++) {
        int c = tid + j * 256, r = c >> 3, ch = c & 7;
        sA[j] = swz128(r, ch);
        gA[j] = (uint32_t)(rowBase + r) * KD + ch * 8;
    }
#pragma unroll
    for (int j = 0; j < 4; j++) {
        int c = tid + j * 256, r = c >> 3, ch = c & 7;
        sB[j] = swz128(r, ch);
        gB[j] = (uint32_t)(colBase + r) * KD + ch * 8;
    }

    auto issue = [&](int kt, int s) {
        char* st = sm + s * SSTAGE;
        const uint32_t kof = kt * BK;
#pragma unroll
        for (int j = 0; j < 8; j++)
            cp16(st + sA[j], Asig + gA[j] + kof);
#pragma unroll
        for (int j = 0; j < 4; j++)
            cp16(st + A_PLANE + sB[j], Bj + gB[j] + kof);
        asm volatile("cp.async.commit_group;\n");
    };

    const int arowl = lane & 15;
    const int browl = ((lane >> 4) << 3) + (lane & 7);
    const int ac0 = lane >> 4, bc0 = (lane >> 3) & 1;

    constexpr int KT = KD / BK;  // 8
    issue(0, 0);
    issue(1, 1);

    for (int kt = 0; kt < KT; kt++) {
        const int buf = kt % NS;
        if (kt + 2 < KT) {
            issue(kt + 2, (kt + 2) % NS);
            asm volatile("cp.async.wait_group 2;\n");
        } else if (kt + 1 < KT) {
            asm volatile("cp.async.wait_group 1;\n");
        } else {
            asm volatile("cp.async.wait_group 0;\n");
        }
        __syncthreads();
        char* st = sm + buf * SSTAGE;

#pragma unroll
        for (int k16 = 0; k16 < 4; k16++) {
            uint32_t ah[4][4], bb[4][4];
#pragma unroll
            for (int mi = 0; mi < 4; mi++)
                ldsm4(ah[mi], st + swz128(wm * 64 + mi * 16 + arowl, k16 * 2 + ac0));
#pragma unroll
            for (int g = 0; g < 4; g++)
                ldsm4(bb[g], st + A_PLANE +
                              swz128(wn * 64 + g * 16 + browl, k16 * 2 + bc0));
#pragma unroll
            for (int ni = 0; ni < 8; ni++) {
                const uint32_t* b = &bb[ni >> 1][(ni & 1) * 2];
#pragma unroll
                for (int mi = 0; mi < 4; mi++) mma_fp16(acc[mi][ni], ah[mi], b);
            }
        }
        __syncthreads();
    }

    const int lrow = lane >> 2, lcol = lane & 3;
#pragma unroll
    for (int mi = 0; mi < 4; mi++) {
#pragma unroll
        for (int ni = 0; ni < 8; ni++) {
            const int gr = rowBase + wm * 64 + mi * 16 + lrow;
            const int gc = colBase + wn * 64 + ni * 8 + lcol * 2;
            const uint32_t i0 = (uint32_t)gr * ADIM + gc;
            const uint32_t i1 = i0 + 8 * ADIM;
            const float2 d0 = *(const float2*)(aux + i0);
            const float2 d1 = *(const float2*)(aux + i1);
            float v0 = fast_tanh(fmaf(acc[mi][ni][0], INV_TAU, d0.x));
            float v1 = fast_tanh(fmaf(acc[mi][ni][1], INV_TAU, d0.y));
            float v2 = fast_tanh(fmaf(acc[mi][ni][2], INV_TAU, d1.x));
            float v3 = fast_tanh(fmaf(acc[mi][ni][3], INV_TAU, d1.y));
            if (MODE == 1) {
                *(__half2*)(osig + i0) = __halves2half2(__float2half_rn(v0), __float2half_rn(v1));
                *(__half2*)(osig + i1) = __halves2half2(__float2half_rn(v2), __float2half_rn(v3));
            } else {
                *(float2*)(of32 + i0) = make_float2(v0, v1);
                *(float2*)(of32 + i1) = make_float2(v2, v3);
            }
        }
    }
}

extern "C" void kernel_launch(void* const* d_in, const int* in_sizes, int n_in,
                              void* d_out, int out_size) {
    (void)in_sizes; (void)n_in; (void)out_size;
    const float* x = (const float*)d_in[0];  // [16384, 1024]
    const float* W = (const float*)d_in[1];  // [512, 1024]
    const float* b = (const float*)d_in[2];  // [512]
    const float* J = (const float*)d_in[3];  // [512, 512]
    float* out = (float*)d_out;              // [16384, 512]

    cudaFuncSetAttribute((const void*)drive_gemm,
                         cudaFuncAttributeMaxDynamicSharedMemorySize, SMEM_DRIVE);
    cudaFuncSetAttribute((const void*)settle_fp16<1>,
                         cudaFuncAttributeMaxDynamicSharedMemorySize, SMEM_SETTLE);
    cudaFuncSetAttribute((const void*)settle_fp16<2>,
                         cudaFuncAttributeMaxDynamicSharedMemorySize, SMEM_SETTLE);

    __half *xh, *xl, *wh, *jh, *s0, *s1;
    float* drv;
    cudaGetSymbolAddress((void**)&xh, g_xh);
    cudaGetSymbolAddress((void**)&xl, g_xl);
    cudaGetSymbolAddress((void**)&wh, g_wh);
    cudaGetSymbolAddress((void**)&jh, g_jh);
    cudaGetSymbolAddress((void**)&s0, g_s0);
    cudaGetSymbolAddress((void**)&s1, g_s1);
    cudaGetSymbolAddress((void**)&drv, g_drive);

    {
        int n4 = BDIM * MDIM / 4;
        split_h<<<(n4 + 255) / 256, 256>>>((const float4*)x, (uint2*)xh, (uint2*)xl, n4);
        n4 = ADIM * MDIM / 4;
        trunc_h<<<(n4 + 255) / 256, 256>>>((const float4*)W, (uint2*)wh, n4);
        n4 = ADIM * ADIM / 4;
        trunc_h<<<(n4 + 255) / 256, 256>>>((const float4*)J, (uint2*)jh, n4);
    }

    dim3 grid(ADIM / BN, BDIM / BM);  // (4, 64) = 256 CTAs

    // drive = x@W^T + b (fp32); sigma1 = tanh(drive) -> fp16
    drive_gemm<<<grid, 256, SMEM_DRIVE>>>(xh, xl, wh, b, drv, s0);

    // sigma2..sigma9
    __half* S[2] = {s0, s1};
    for (int i = 0; i < 8; i++) {
        settle_fp16<1><<<grid, 256, SMEM_SETTLE>>>(S[i & 1], jh, drv, S[(i + 1) & 1],
                                                   nullptr);
    }
    // sigma10 -> d_out (fp32)
    settle_fp16<2><<<grid, 256, SMEM_SETTLE>>>(s0, jh, drv, nullptr, out);
}

// round 17
// speedup vs baseline: 1.1508x; 1.1508x over previous
#include <cuda_runtime.h>
#include <cuda_fp16.h>
#include <cstdint>
#include <cstddef>

#define BDIM 16384
#define ADIM 512
#define MDIM 1024
#define INV_TAU 10.0f

constexpr int BM = 128, BN = 128, BK = 64;
constexpr int PLANE128_B = 128 * 128;      // 16 KB (128 rows x 128 B)
constexpr int STAGE_B = 2 * PLANE128_B;    // A + B = 32 KB
constexpr int NS = 3;
constexpr int SMEM_RQ = NS * STAGE_B;      // 96 KB  (x2 CTAs/SM = 192 KB)

// ---- device scratch (allocation-free rule) ----
__device__ __align__(128) __half g_xh[(size_t)BDIM * MDIM];   // fp16 x
__device__ __align__(128) __half g_wh[(size_t)ADIM * MDIM];   // fp16 W
__device__ __align__(128) __half g_jh[(size_t)ADIM * ADIM];   // fp16 J
__device__ __align__(128) float g_drive[(size_t)BDIM * ADIM];
__device__ __align__(128) __half g_s0[(size_t)BDIM * ADIM];
__device__ __align__(128) __half g_s1[(size_t)BDIM * ADIM];

// ---- helpers ----
__device__ __forceinline__ void cp16(void* sdst, const void* gsrc) {
    uint32_t s = (uint32_t)__cvta_generic_to_shared(sdst);
    asm volatile("cp.async.cg.shared.global [%0], [%1], 16;\n" ::"r"(s), "l"(gsrc));
}

__device__ __forceinline__ void ldsm4(uint32_t* r, const void* p) {
    uint32_t a = (uint32_t)__cvta_generic_to_shared(p);
    asm volatile("ldmatrix.sync.aligned.m8n8.x4.shared.b16 {%0,%1,%2,%3}, [%4];\n"
                 : "=r"(r[0]), "=r"(r[1]), "=r"(r[2]), "=r"(r[3])
                 : "r"(a));
}

__device__ __forceinline__ void mma_fp16(float* c, const uint32_t* a, const uint32_t* b) {
    asm volatile(
        "mma.sync.aligned.m16n8k16.row.col.f32.f16.f16.f32 "
        "{%0,%1,%2,%3}, {%4,%5,%6,%7}, {%8,%9}, {%0,%1,%2,%3};\n"
        : "+f"(c[0]), "+f"(c[1]), "+f"(c[2]), "+f"(c[3])
        : "r"(a[0]), "r"(a[1]), "r"(a[2]), "r"(a[3]), "r"(b[0]), "r"(b[1]));
}

// 128B-row swizzle: rows of 64 fp16, 8 chunks of 16B
__device__ __forceinline__ uint32_t swz128(int r, int ch) {
    return (uint32_t)(r * 128 + ((ch ^ (r & 7)) << 4));
}

__device__ __forceinline__ float fast_tanh(float x) {
    float e, r;
    asm("ex2.approx.f32 %0, %1;" : "=f"(e) : "f"(x * 2.8853901817f));  // 2*log2(e)*x
    asm("rcp.approx.f32 %0, %1;" : "=f"(r) : "f"(e + 1.0f));
    return fmaf(-2.0f, r, 1.0f);
}

// ---- truncate fp32 -> fp16 (x, W, J) ----
__global__ void trunc_h(const float4* __restrict__ src, uint2* __restrict__ dst, int n4) {
    int i = blockIdx.x * blockDim.x + threadIdx.x;
    if (i >= n4) return;
    float4 v = src[i];
    __half2 a = __halves2half2(__float2half_rn(v.x), __float2half_rn(v.y));
    __half2 b = __halves2half2(__float2half_rn(v.z), __float2half_rn(v.w));
    dst[i] = make_uint2(*(uint32_t*)&a, *(uint32_t*)&b);
}

// ========== unified GEMM: C[16384 x 512] = A[16384 x KD] @ B[512 x KD]^T ==========
// MODE 0 (drive):  d = C + aux(bias);  of32 = d;  osig = tanh(d) fp16
// MODE 1 (mid):    osig = tanh(aux + C*INV_TAU) fp16       (aux = drive)
// MODE 2 (final):  of32 = tanh(aux + C*INV_TAU) fp32
template <int KD, int MODE>
__global__ void __launch_bounds__(256, 2)
gemm_step(const __half* __restrict__ Ah, const __half* __restrict__ Bh,
          const float* __restrict__ aux, __half* __restrict__ osig,
          float* __restrict__ of32) {
    extern __shared__ char sm[];
    const int tid = threadIdx.x, lane = tid & 31, wid = tid >> 5;
    const int wm = wid & 3, wn = wid >> 2;     // 4x2 warps, 32x64 tiles
    const int rowBase = blockIdx.y * BM, colBase = blockIdx.x * BN;

    float acc[2][8][4];
#pragma unroll
    for (int mi = 0; mi < 2; mi++)
#pragma unroll
        for (int ni = 0; ni < 8; ni++)
#pragma unroll
            for (int q = 0; q < 4; q++) acc[mi][ni][q] = 0.f;

    // producers: 1024 16B-chunks per plane, 4 per thread
    uint32_t sO[4], gA[4], gB[4];
#pragma unroll
    for (int j = 0; j < 4; j++) {
        int c = tid + j * 256;
        int r = c >> 3, ch = c & 7;
        sO[j] = swz128(r, ch);
        gA[j] = (uint32_t)(rowBase + r) * KD + ch * 8;
        gB[j] = (uint32_t)(colBase + r) * KD + ch * 8;
    }

    auto issue = [&](int kt, int s) {
        char* st = sm + s * STAGE_B;
        const uint32_t kof = kt * BK;
#pragma unroll
        for (int j = 0; j < 4; j++) {
            cp16(st + sO[j], Ah + gA[j] + kof);
            cp16(st + PLANE128_B + sO[j], Bh + gB[j] + kof);
        }
        asm volatile("cp.async.commit_group;\n");
    };

    const int arowl = lane & 15;
    const int browl = ((lane >> 4) << 3) + (lane & 7);
    uint32_t aOff[4][2], bOff[4][4];
#pragma unroll
    for (int k16 = 0; k16 < 4; k16++) {
        const int achunk = k16 * 2 + (lane >> 4);
        const int bchunk = k16 * 2 + ((lane >> 3) & 1);
#pragma unroll
        for (int mi = 0; mi < 2; mi++)
            aOff[k16][mi] = swz128(wm * 32 + mi * 16 + arowl, achunk);
#pragma unroll
        for (int g = 0; g < 4; g++)
            bOff[k16][g] = swz128(wn * 64 + g * 16 + browl, bchunk);
    }

    constexpr int KT = KD / BK;  // 16 (drive) / 8 (settle)
    issue(0, 0);
    issue(1, 1);

    for (int kt = 0; kt < KT; kt++) {
        const int buf = kt % NS;
        if (kt + 2 < KT) {
            issue(kt + 2, (kt + 2) % NS);
            asm volatile("cp.async.wait_group 2;\n");
        } else if (kt + 1 < KT) {
            asm volatile("cp.async.wait_group 1;\n");
        } else {
            asm volatile("cp.async.wait_group 0;\n");
        }
        __syncthreads();
        char* st = sm + buf * STAGE_B;

#pragma unroll
        for (int k16 = 0; k16 < 4; k16++) {
            uint32_t ah[2][4], bb[4][4];
#pragma unroll
            for (int mi = 0; mi < 2; mi++)
                ldsm4(ah[mi], st + aOff[k16][mi]);
#pragma unroll
            for (int g = 0; g < 4; g++)
                ldsm4(bb[g], st + PLANE128_B + bOff[k16][g]);
#pragma unroll
            for (int ni = 0; ni < 8; ni++) {
                const uint32_t* b = &bb[ni >> 1][(ni & 1) * 2];
                mma_fp16(acc[0][ni], ah[0], b);
                mma_fp16(acc[1][ni], ah[1], b);
            }
        }
        __syncthreads();
    }

    // ---- epilogue ----
    const int lrow = lane >> 2, lcol = lane & 3;
#pragma unroll
    for (int mi = 0; mi < 2; mi++) {
#pragma unroll
        for (int ni = 0; ni < 8; ni++) {
            const int gr = rowBase + wm * 32 + mi * 16 + lrow;
            const int gc = colBase + wn * 64 + ni * 8 + lcol * 2;
            const uint32_t i0 = (uint32_t)gr * ADIM + gc;
            const uint32_t i1 = i0 + 8 * ADIM;
            if (MODE == 0) {
                const float b0 = aux[gc], b1 = aux[gc + 1];
                float v0 = acc[mi][ni][0] + b0, v1 = acc[mi][ni][1] + b1;
                float v2 = acc[mi][ni][2] + b0, v3 = acc[mi][ni][3] + b1;
                *(float2*)(of32 + i0) = make_float2(v0, v1);
                *(float2*)(of32 + i1) = make_float2(v2, v3);
                *(__half2*)(osig + i0) = __halves2half2(__float2half_rn(fast_tanh(v0)),
                                                        __float2half_rn(fast_tanh(v1)));
                *(__half2*)(osig + i1) = __halves2half2(__float2half_rn(fast_tanh(v2)),
                                                        __float2half_rn(fast_tanh(v3)));
            } else {
                const float2 d0 = *(const float2*)(aux + i0);
                const float2 d1 = *(const float2*)(aux + i1);
                float v0 = fast_tanh(fmaf(acc[mi][ni][0], INV_TAU, d0.x));
                float v1 = fast_tanh(fmaf(acc[mi][ni][1], INV_TAU, d0.y));
                float v2 = fast_tanh(fmaf(acc[mi][ni][2], INV_TAU, d1.x));
                float v3 = fast_tanh(fmaf(acc[mi][ni][3], INV_TAU, d1.y));
                if (MODE == 1) {
                    *(__half2*)(osig + i0) =
                        __halves2half2(__float2half_rn(v0), __float2half_rn(v1));
                    *(__half2*)(osig + i1) =
                        __halves2half2(__float2half_rn(v2), __float2half_rn(v3));
                } else {
                    *(float2*)(of32 + i0) = make_float2(v0, v1);
                    *(float2*)(of32 + i1) = make_float2(v2, v3);
                }
            }
        }
    }
}

extern "C" void kernel_launch(void* const* d_in, const int* in_sizes, int n_in,
                              void* d_out, int out_size) {
    (void)in_sizes; (void)n_in; (void)out_size;
    const float* x = (const float*)d_in[0];  // [16384, 1024]
    const float* W = (const float*)d_in[1];  // [512, 1024]
    const float* b = (const float*)d_in[2];  // [512]
    const float* J = (const float*)d_in[3];  // [512, 512]
    float* out = (float*)d_out;              // [16384, 512]

    cudaFuncSetAttribute((const void*)gemm_step<MDIM, 0>,
                         cudaFuncAttributeMaxDynamicSharedMemorySize, SMEM_RQ);
    cudaFuncSetAttribute((const void*)gemm_step<ADIM, 1>,
                         cudaFuncAttributeMaxDynamicSharedMemorySize, SMEM_RQ);
    cudaFuncSetAttribute((const void*)gemm_step<ADIM, 2>,
                         cudaFuncAttributeMaxDynamicSharedMemorySize, SMEM_RQ);

    __half *xh, *wh, *jh, *s0, *s1;
    float* drv;
    cudaGetSymbolAddress((void**)&xh, g_xh);
    cudaGetSymbolAddress((void**)&wh, g_wh);
    cudaGetSymbolAddress((void**)&jh, g_jh);
    cudaGetSymbolAddress((void**)&s0, g_s0);
    cudaGetSymbolAddress((void**)&s1, g_s1);
    cudaGetSymbolAddress((void**)&drv, g_drive);

    {
        int n4 = BDIM * MDIM / 4;
        trunc_h<<<(n4 + 255) / 256, 256>>>((const float4*)x, (uint2*)xh, n4);
        n4 = ADIM * MDIM / 4;
        trunc_h<<<(n4 + 255) / 256, 256>>>((const float4*)W, (uint2*)wh, n4);
        n4 = ADIM * ADIM / 4;
        trunc_h<<<(n4 + 255) / 256, 256>>>((const float4*)J, (uint2*)jh, n4);
    }

    dim3 grid(ADIM / BN, BDIM / BM);  // (4, 128) = 512 CTAs

    // drive = x@W^T + b (fp32); sigma1 = tanh(drive) -> fp16
    gemm_step<MDIM, 0><<<grid, 256, SMEM_RQ>>>(xh, wh, b, s0, drv);

    // sigma2..sigma9 (8 mid steps, ping-pong)
    __half* S[2] = {s0, s1};
    for (int i = 0; i < 8; i++) {
        gemm_step<ADIM, 1><<<grid, 256, SMEM_RQ>>>(S[i & 1], jh, drv, S[(i + 1) & 1],
                                                   nullptr);
    }
    // sigma10 -> d_out (fp32)
    gemm_step<ADIM, 2><<<grid, 256, SMEM_RQ>>>(s0, jh, drv, nullptr, out);
}